// round 1
// baseline (speedup 1.0000x reference)
#include <cuda_runtime.h>
#include <cstdint>

#define NR 4096            // output rows (N of GEMM)
#define NC 4096            // input cols  (K of GEMM)

#define BM 128
#define BN 128
#define BK 16
#define PAD 8
#define LDS_A (BM + PAD)   // 136 floats
#define LDS_B (BN + PAD)   // 136 floats

// Dense scatter target for the sparse weights. 64 MB static device global
// (allowed; no cudaMalloc anywhere).
__device__ float g_W[(size_t)NR * NC];

// ---------------------------------------------------------------------------
// Kernel 1: zero W (graph replays re-run the scatter, so W must be re-zeroed
// every launch).
// ---------------------------------------------------------------------------
__global__ void zero_w_kernel() {
    size_t i = ((size_t)blockIdx.x * blockDim.x + threadIdx.x) * 4;
    float4 z = make_float4(0.f, 0.f, 0.f, 0.f);
    *reinterpret_cast<float4*>(g_W + i) = z;
}

// ---------------------------------------------------------------------------
// Kernel 2: scatter values into W. Duplicates exist (random indices, and the
// reference uses .add), so atomicAdd is required for correctness.
// ---------------------------------------------------------------------------
__global__ void scatter_kernel(const float* __restrict__ values,
                               const int* __restrict__ col_idx,
                               const int* __restrict__ row_ids,
                               int nnz) {
    int i = blockIdx.x * blockDim.x + threadIdx.x;
    if (i < nnz) {
        atomicAdd(&g_W[(size_t)row_ids[i] * NC + col_idx[i]], values[i]);
    }
}

// ---------------------------------------------------------------------------
// TF32 helpers
// ---------------------------------------------------------------------------
__device__ __forceinline__ float cvt_tf32(float x) {
    uint32_t u;
    asm("cvt.rna.tf32.f32 %0, %1;" : "=r"(u) : "f"(x));
    return __uint_as_float(u);
}

__device__ __forceinline__ void mma_tf32(float* c, const uint32_t* a, const uint32_t* b) {
    asm volatile(
        "mma.sync.aligned.m16n8k8.row.col.f32.tf32.tf32.f32 "
        "{%0,%1,%2,%3}, {%4,%5,%6,%7}, {%8,%9}, {%0,%1,%2,%3};"
        : "+f"(c[0]), "+f"(c[1]), "+f"(c[2]), "+f"(c[3])
        : "r"(a[0]), "r"(a[1]), "r"(a[2]), "r"(a[3]),
          "r"(b[0]), "r"(b[1]));
}

// ---------------------------------------------------------------------------
// Kernel 3: C[M,NR] = X[M,NC] * W[NR,NC]^T  (both operands K-contiguous)
// Tiling: 128x128x16, 256 threads (8 warps as 4(m) x 2(n), warp tile 32x64),
// mma.m16n8k8 TF32, double-buffered SMEM, k-major padded layout.
// ---------------------------------------------------------------------------
__global__ __launch_bounds__(256, 2)
void gemm_tf32_kernel(const float* __restrict__ X, float* __restrict__ O, int M) {
    __shared__ float sA[2][BK][LDS_A];
    __shared__ float sB[2][BK][LDS_B];

    const int tid   = threadIdx.x;
    const int warp  = tid >> 5;
    const int lane  = tid & 31;
    const int wm    = warp >> 1;       // 0..3  -> m offset wm*32
    const int wn    = warp & 1;        // 0..1  -> n offset wn*64
    const int group = lane >> 2;       // 0..7
    const int t4    = lane & 3;        // 0..3

    const int bm = blockIdx.y * BM;
    const int bn = blockIdx.x * BN;

    // global->shared load mapping: 512 float4 per tile, 2 per thread
    const int lrow = tid & 63;         // 0..63 (second pass += 64)
    const int lc4  = tid >> 6;         // 0..3 -> k chunk lc4*4

    const float* Ag = X   + (size_t)(bm + lrow) * NC + lc4 * 4;
    const float* Bg = g_W + (size_t)(bn + lrow) * NC + lc4 * 4;
    const size_t rowstep = (size_t)64 * NC;

    float acc[2][8][4];
#pragma unroll
    for (int i = 0; i < 2; i++)
#pragma unroll
        for (int j = 0; j < 8; j++)
#pragma unroll
            for (int v = 0; v < 4; v++) acc[i][j][v] = 0.f;

    float4 ra[2], rb[2];

    // prologue: stage tile 0
#pragma unroll
    for (int p = 0; p < 2; p++) {
        ra[p] = *reinterpret_cast<const float4*>(Ag + p * rowstep);
        rb[p] = *reinterpret_cast<const float4*>(Bg + p * rowstep);
    }
#pragma unroll
    for (int p = 0; p < 2; p++) {
        int r = lrow + p * 64;
        sA[0][lc4 * 4 + 0][r] = cvt_tf32(ra[p].x);
        sA[0][lc4 * 4 + 1][r] = cvt_tf32(ra[p].y);
        sA[0][lc4 * 4 + 2][r] = cvt_tf32(ra[p].z);
        sA[0][lc4 * 4 + 3][r] = cvt_tf32(ra[p].w);
        sB[0][lc4 * 4 + 0][r] = cvt_tf32(rb[p].x);
        sB[0][lc4 * 4 + 1][r] = cvt_tf32(rb[p].y);
        sB[0][lc4 * 4 + 2][r] = cvt_tf32(rb[p].z);
        sB[0][lc4 * 4 + 3][r] = cvt_tf32(rb[p].w);
    }
    __syncthreads();

    const int KT = NC / BK;  // 256 k-tiles

    for (int kk = 0; kk < KT; kk++) {
        const int buf = kk & 1;

        // prefetch next tile into registers (hidden under compute)
        if (kk + 1 < KT) {
            const float* A2 = Ag + (kk + 1) * BK;
            const float* B2 = Bg + (kk + 1) * BK;
#pragma unroll
            for (int p = 0; p < 2; p++) {
                ra[p] = *reinterpret_cast<const float4*>(A2 + p * rowstep);
                rb[p] = *reinterpret_cast<const float4*>(B2 + p * rowstep);
            }
        }

        // compute current tile: 2 k-steps of 8
#pragma unroll
        for (int ks = 0; ks < 2; ks++) {
            const int k0 = ks * 8;
            uint32_t af[2][4];
            uint32_t bf[8][2];
#pragma unroll
            for (int i = 0; i < 2; i++) {
                int m = wm * 32 + i * 16 + group;
                af[i][0] = __float_as_uint(sA[buf][k0 + t4][m]);
                af[i][1] = __float_as_uint(sA[buf][k0 + t4][m + 8]);
                af[i][2] = __float_as_uint(sA[buf][k0 + t4 + 4][m]);
                af[i][3] = __float_as_uint(sA[buf][k0 + t4 + 4][m + 8]);
            }
#pragma unroll
            for (int j = 0; j < 8; j++) {
                int n = wn * 64 + j * 8 + group;
                bf[j][0] = __float_as_uint(sB[buf][k0 + t4][n]);
                bf[j][1] = __float_as_uint(sB[buf][k0 + t4 + 4][n]);
            }
#pragma unroll
            for (int i = 0; i < 2; i++)
#pragma unroll
                for (int j = 0; j < 8; j++)
                    mma_tf32(acc[i][j], af[i], bf[j]);
        }

        // commit next tile to the other buffer
        if (kk + 1 < KT) {
            const int nb = buf ^ 1;
#pragma unroll
            for (int p = 0; p < 2; p++) {
                int r = lrow + p * 64;
                sA[nb][lc4 * 4 + 0][r] = cvt_tf32(ra[p].x);
                sA[nb][lc4 * 4 + 1][r] = cvt_tf32(ra[p].y);
                sA[nb][lc4 * 4 + 2][r] = cvt_tf32(ra[p].z);
                sA[nb][lc4 * 4 + 3][r] = cvt_tf32(ra[p].w);
                sB[nb][lc4 * 4 + 0][r] = cvt_tf32(rb[p].x);
                sB[nb][lc4 * 4 + 1][r] = cvt_tf32(rb[p].y);
                sB[nb][lc4 * 4 + 2][r] = cvt_tf32(rb[p].z);
                sB[nb][lc4 * 4 + 3][r] = cvt_tf32(rb[p].w);
            }
        }
        __syncthreads();
    }

    // epilogue: c0,c1 = (row, 2t4 / 2t4+1); c2,c3 = row+8 — pairwise float2 STG
#pragma unroll
    for (int i = 0; i < 2; i++) {
        int row = bm + wm * 32 + i * 16 + group;
#pragma unroll
        for (int j = 0; j < 8; j++) {
            int col = bn + wn * 64 + j * 8 + t4 * 2;
            float2 lo = make_float2(acc[i][j][0], acc[i][j][1]);
            float2 hi = make_float2(acc[i][j][2], acc[i][j][3]);
            *reinterpret_cast<float2*>(O + (size_t)row * NR + col)       = lo;
            *reinterpret_cast<float2*>(O + (size_t)(row + 8) * NR + col) = hi;
        }
    }
}

// ---------------------------------------------------------------------------
// kernel_launch: zero -> scatter -> GEMM (all on the capture stream)
// ---------------------------------------------------------------------------
extern "C" void kernel_launch(void* const* d_in, const int* in_sizes, int n_in,
                              void* d_out, int out_size) {
    const float* x      = (const float*)d_in[0];
    const float* values = (const float*)d_in[1];
    const int*   cols   = (const int*)d_in[2];
    const int*   rows   = (const int*)d_in[3];
    float*       out    = (float*)d_out;

    const int nnz = in_sizes[1];
    const int M   = in_sizes[0] / NC;   // 8192

    // 1) zero W: 16M floats, float4 per thread
    {
        const size_t total4 = ((size_t)NR * NC) / 4;
        int threads = 256;
        int blocks  = (int)(total4 / threads);
        zero_w_kernel<<<blocks, threads>>>();
    }

    // 2) scatter
    {
        int threads = 256;
        int blocks  = (nnz + threads - 1) / threads;
        scatter_kernel<<<blocks, threads>>>(values, cols, rows, nnz);
    }

    // 3) GEMM
    {
        dim3 grid(NR / BN, M / BM);   // (32, 64): x-dim over N so concurrent
                                      // blocks share the A panel in L2
        gemm_tf32_kernel<<<grid, 256>>>(x, out, M);
    }
}

// round 3
// speedup vs baseline: 4.8545x; 4.8545x over previous
#include <cuda_runtime.h>
#include <cuda_fp16.h>
#include <cstdint>

#define K_DIM 4096
#define N_DIM 4096
#define M_MAX 8192

#define BM 128
#define BN 128
#define BK 32              // halves per k-tile (64 bytes per row)
#define STAGES 4
#define KTILES (K_DIM / BK)   // 128

#define A_BYTES (BM * BK * 2)            // 8192
#define B_BYTES (BN * BK * 2)            // 8192
#define STAGE_BYTES (A_BYTES + B_BYTES)  // 16384
#define SMEM_TOTAL (STAGES * STAGE_BYTES)  // 65536

__device__ float  g_W [(size_t)N_DIM * K_DIM];
__device__ __align__(16) __half g_Wh[(size_t)N_DIM * K_DIM];
__device__ __align__(16) __half g_Xh[(size_t)M_MAX * K_DIM];

// ---------------------------------------------------------------------------
// helpers
// ---------------------------------------------------------------------------
__device__ __forceinline__ uint32_t smem_u32(const void* p) {
    uint32_t a;
    asm("{ .reg .u64 t; cvta.to.shared.u64 t, %1; cvt.u32.u64 %0, t; }"
        : "=r"(a) : "l"(p));
    return a;
}

// swizzled byte offset inside one operand tile.
// row: 0..127 (64B rows), c: 16B chunk 0..3.
__device__ __forceinline__ uint32_t swz(int row, int c) {
    int line = row >> 1;
    int slot = (((row & 1) << 2) | c) ^ (line & 7);
    return (uint32_t)(line * 128 + slot * 16);
}

#define CP16(dst, src) \
    asm volatile("cp.async.cg.shared.global [%0], [%1], 16;" \
                 :: "r"(dst), "l"(src) : "memory")
#define CP_COMMIT() asm volatile("cp.async.commit_group;" ::: "memory")
#define CP_WAIT(n)  asm volatile("cp.async.wait_group %0;" :: "n"(n) : "memory")

#define LDSM_X4(r0, r1, r2, r3, addr)                                       \
    asm volatile("ldmatrix.sync.aligned.m8n8.x4.shared.b16 {%0,%1,%2,%3}, [%4];" \
                 : "=r"(r0), "=r"(r1), "=r"(r2), "=r"(r3) : "r"(addr))

__device__ __forceinline__ void mma_fp16(float* c, const uint32_t* a,
                                         uint32_t b0, uint32_t b1) {
    asm volatile(
        "mma.sync.aligned.m16n8k16.row.col.f32.f16.f16.f32 "
        "{%0,%1,%2,%3}, {%4,%5,%6,%7}, {%8,%9}, {%0,%1,%2,%3};"
        : "+f"(c[0]), "+f"(c[1]), "+f"(c[2]), "+f"(c[3])
        : "r"(a[0]), "r"(a[1]), "r"(a[2]), "r"(a[3]), "r"(b0), "r"(b1));
}

// ---------------------------------------------------------------------------
// prep kernels
// ---------------------------------------------------------------------------
__global__ void zero_w_kernel() {
    size_t i = ((size_t)blockIdx.x * blockDim.x + threadIdx.x) * 4;
    *reinterpret_cast<float4*>(g_W + i) = make_float4(0.f, 0.f, 0.f, 0.f);
}

__global__ void scatter_kernel(const float* __restrict__ values,
                               const int* __restrict__ col_idx,
                               const int* __restrict__ row_ids, int nnz) {
    int i = blockIdx.x * blockDim.x + threadIdx.x;
    if (i < nnz)
        atomicAdd(&g_W[(size_t)row_ids[i] * K_DIM + col_idx[i]], values[i]);
}

__global__ void conv_w_kernel() {
    size_t i = ((size_t)blockIdx.x * blockDim.x + threadIdx.x) * 8;
    float4 v0 = *reinterpret_cast<const float4*>(g_W + i);
    float4 v1 = *reinterpret_cast<const float4*>(g_W + i + 4);
    __half2 h[4];
    h[0] = __floats2half2_rn(v0.x, v0.y);
    h[1] = __floats2half2_rn(v0.z, v0.w);
    h[2] = __floats2half2_rn(v1.x, v1.y);
    h[3] = __floats2half2_rn(v1.z, v1.w);
    *reinterpret_cast<uint4*>(g_Wh + i) = *reinterpret_cast<uint4*>(h);
}

__global__ void conv_x_kernel(const float* __restrict__ x) {
    size_t i = ((size_t)blockIdx.x * blockDim.x + threadIdx.x) * 8;
    float4 v0 = *reinterpret_cast<const float4*>(x + i);
    float4 v1 = *reinterpret_cast<const float4*>(x + i + 4);
    __half2 h[4];
    h[0] = __floats2half2_rn(v0.x, v0.y);
    h[1] = __floats2half2_rn(v0.z, v0.w);
    h[2] = __floats2half2_rn(v1.x, v1.y);
    h[3] = __floats2half2_rn(v1.z, v1.w);
    *reinterpret_cast<uint4*>(g_Xh + i) = *reinterpret_cast<uint4*>(h);
}

// ---------------------------------------------------------------------------
// GEMM: O[M, N_DIM] = Xh[M, K] * Wh[N, K]^T  (fp16 in, fp32 accum/out)
// CTA 128x128, BK=32, 4-stage cp.async, 8 warps as 4(m) x 2(n): warp 32x64.
// ---------------------------------------------------------------------------
__global__ __launch_bounds__(256, 2)
void gemm_fp16_kernel(float* __restrict__ O) {
    extern __shared__ char smem[];
    const uint32_t sb = smem_u32(smem);

    const int tid  = threadIdx.x;
    const int warp = tid >> 5;
    const int lane = tid & 31;
    const int wm   = warp >> 1;          // 0..3
    const int wn   = warp & 1;           // 0..1
    const int bm   = blockIdx.y * BM;
    const int bn   = blockIdx.x * BN;

    // ---- producer mapping: 512 16B chunks per operand, 2 per thread ----
    const int prow0 = tid >> 2;          // 0..63
    const int pc    = tid & 3;           // chunk 0..3
    const int prow1 = prow0 + 64;

    const __half* paG0 = g_Xh + (size_t)(bm + prow0) * K_DIM + pc * 8;
    const __half* paG1 = g_Xh + (size_t)(bm + prow1) * K_DIM + pc * 8;
    const __half* pbG0 = g_Wh + (size_t)(bn + prow0) * K_DIM + pc * 8;
    const __half* pbG1 = g_Wh + (size_t)(bn + prow1) * K_DIM + pc * 8;

    const uint32_t dA0 = swz(prow0, pc), dA1 = swz(prow1, pc);
    const uint32_t dB0 = swz(prow0, pc), dB1 = swz(prow1, pc);

    // ---- consumer (ldmatrix) address offsets within a stage ----
    // A: per (mi, ks): rows wm*32+mi*16+(lane&15), chunk ks*2+(lane>>4)
    uint32_t aoff[2][2];
#pragma unroll
    for (int mi = 0; mi < 2; mi++)
#pragma unroll
        for (int ks = 0; ks < 2; ks++)
            aoff[mi][ks] = swz(wm * 32 + mi * 16 + (lane & 15),
                               ks * 2 + (lane >> 4));
    // B: per (u, ks, h): rows wn*64+u*32+lane, chunk ks*2+h
    uint32_t boff[2][2][2];
#pragma unroll
    for (int u = 0; u < 2; u++)
#pragma unroll
        for (int ks = 0; ks < 2; ks++)
#pragma unroll
            for (int h = 0; h < 2; h++)
                boff[u][ks][h] = swz(wn * 64 + u * 32 + lane, ks * 2 + h);

    float acc[2][8][4];
#pragma unroll
    for (int i = 0; i < 2; i++)
#pragma unroll
        for (int j = 0; j < 8; j++)
#pragma unroll
            for (int v = 0; v < 4; v++) acc[i][j][v] = 0.f;

    // ---- prologue: stages 0..STAGES-2 ----
#pragma unroll
    for (int s = 0; s < STAGES - 1; s++) {
        const uint32_t ab = sb + s * STAGE_BYTES;
        const uint32_t bb = ab + A_BYTES;
        const size_t ko = (size_t)s * BK;
        CP16(ab + dA0, paG0 + ko);
        CP16(ab + dA1, paG1 + ko);
        CP16(bb + dB0, pbG0 + ko);
        CP16(bb + dB1, pbG1 + ko);
        CP_COMMIT();
    }

    for (int kk = 0; kk < KTILES; kk++) {
        CP_WAIT(STAGES - 2);
        __syncthreads();

        // issue loads for tile kk+STAGES-1 (or empty group to keep counts)
        if (kk + STAGES - 1 < KTILES) {
            const int s = (kk + STAGES - 1) % STAGES;
            const uint32_t ab = sb + s * STAGE_BYTES;
            const uint32_t bb = ab + A_BYTES;
            const size_t ko = (size_t)(kk + STAGES - 1) * BK;
            CP16(ab + dA0, paG0 + ko);
            CP16(ab + dA1, paG1 + ko);
            CP16(bb + dB0, pbG0 + ko);
            CP16(bb + dB1, pbG1 + ko);
        }
        CP_COMMIT();

        // compute current stage
        const uint32_t ab = sb + (kk % STAGES) * STAGE_BYTES;
        const uint32_t bb = ab + A_BYTES;
#pragma unroll
        for (int ks = 0; ks < 2; ks++) {
            uint32_t af[2][4];
#pragma unroll
            for (int mi = 0; mi < 2; mi++)
                LDSM_X4(af[mi][0], af[mi][1], af[mi][2], af[mi][3],
                        ab + aoff[mi][ks]);
            uint32_t bf[8][2];
#pragma unroll
            for (int u = 0; u < 2; u++)
#pragma unroll
                for (int h = 0; h < 2; h++) {
                    uint32_t r0, r1, r2, r3;
                    LDSM_X4(r0, r1, r2, r3, bb + boff[u][ks][h]);
                    bf[u * 4 + 0][h] = r0;
                    bf[u * 4 + 1][h] = r1;
                    bf[u * 4 + 2][h] = r2;
                    bf[u * 4 + 3][h] = r3;
                }
#pragma unroll
            for (int mi = 0; mi < 2; mi++)
#pragma unroll
                for (int j = 0; j < 8; j++)
                    mma_fp16(acc[mi][j], af[mi], bf[j][0], bf[j][1]);
        }
    }

    // ---- epilogue ----
    const int tr = lane >> 2;            // 0..7
    const int tc = (lane & 3) * 2;
#pragma unroll
    for (int mi = 0; mi < 2; mi++) {
        const int row = bm + wm * 32 + mi * 16 + tr;
        float* o0 = O + (size_t)row * N_DIM;
        float* o1 = O + (size_t)(row + 8) * N_DIM;
#pragma unroll
        for (int j = 0; j < 8; j++) {
            const int col = bn + wn * 64 + j * 8 + tc;
            *reinterpret_cast<float2*>(o0 + col) =
                make_float2(acc[mi][j][0], acc[mi][j][1]);
            *reinterpret_cast<float2*>(o1 + col) =
                make_float2(acc[mi][j][2], acc[mi][j][3]);
        }
    }
}

// ---------------------------------------------------------------------------
extern "C" void kernel_launch(void* const* d_in, const int* in_sizes, int n_in,
                              void* d_out, int out_size) {
    const float* x      = (const float*)d_in[0];
    const float* values = (const float*)d_in[1];
    const int*   cols   = (const int*)d_in[2];
    const int*   rows   = (const int*)d_in[3];
    float*       out    = (float*)d_out;

    const int nnz = in_sizes[1];
    const int M   = in_sizes[0] / K_DIM;   // 8192

    zero_w_kernel<<<(int)(((size_t)N_DIM * K_DIM / 4) / 256), 256>>>();
    scatter_kernel<<<(nnz + 255) / 256, 256>>>(values, cols, rows, nnz);
    conv_w_kernel<<<(int)(((size_t)N_DIM * K_DIM / 8) / 256), 256>>>();
    conv_x_kernel<<<(int)(((size_t)M * K_DIM / 8) / 256), 256>>>(x);

    cudaFuncSetAttribute(gemm_fp16_kernel,
                         cudaFuncAttributeMaxDynamicSharedMemorySize, SMEM_TOTAL);
    dim3 grid(N_DIM / BN, M / BM);   // (32, 64)
    gemm_fp16_kernel<<<grid, 256, SMEM_TOTAL>>>(out);
}